// round 15
// baseline (speedup 1.0000x reference)
#include <cuda_runtime.h>

// Problem constants
#define Nn   100000
#define Ee   800000
#define Gg   4096
#define INF  143
#define Hh   128
#define BN_INV 0.9999950000374997f   // rsqrt(1 + 1e-5)
#define NBLK ((Nn + 1023) / 1024)    // 98 scan blocks
#define KC   16                      // k-tile
#define MT   128                     // M block tile (doubled for B reuse)
#define KT0  160                     // layer-0 K padded to tile multiple
#define WROWS (KT0 + 3 * Hh)         // 544 pre-split weight rows
#define NT0  (KT0 / KC)              // 10 layer-0 tiles
#define NTL  (Hh / KC)               // 8 tiles per later layer
#define NTILES (WROWS / KC)          // 34 weight k-tiles
#define CELLS_PER_TILE (2 * 128 * 4) // [ks][n][tig] cells, 16B each

// Dynamic smem layout (32-bit words): A raw x2 (stride 20), B packed x2
#define SA_STR 20
#define SA_W   (MT * SA_STR)          // 2560
#define SBP_W  (CELLS_PER_TILE * 4)   // 4096
#define SA_OFF(b)  ((b) * SA_W)
#define SBP_OFF(b) (2 * SA_W + (b) * SBP_W)
#define GSMEM_BYTES ((2 * SA_W + 2 * SBP_W) * 4)   // 53248

// ---------------------------------------------------------------------------
// Device scratch
// ---------------------------------------------------------------------------
__device__ __align__(16) float g_h[Nn * Hh];     // h @ W (UNSCALED), per layer
__device__ __align__(16) float g_act[Nn * Hh];   // post BN+ReLU activations
__device__ float g_dis[Nn];
__device__ int   g_deg[Nn];
__device__ int   g_rowptr[Nn + 1];
__device__ int   g_fill[Nn];
__device__ int   g_col[Ee];
__device__ __align__(16) float g_pool[Gg * Hh];
__device__ float g_cnt[Gg];
__device__ int   g_is64;
__device__ int   g_bsum[NBLK];
// Pre-split + PRE-PACKED weights: cell = {bh(k), bh(k+4), bl(k), bl(k+4)}
__device__ __align__(16) unsigned g_wp[NTILES * CELLS_PER_TILE * 4];

// ---------------------------------------------------------------------------
// TF32 / cp.async helpers
// ---------------------------------------------------------------------------
__device__ __forceinline__ unsigned f2tf32(float x) {
    unsigned r;
    asm("cvt.rna.tf32.f32 %0, %1;" : "=r"(r) : "f"(x));
    return r;
}
__device__ __forceinline__ void mma_tf32(float* d, const unsigned* a,
                                         unsigned b0, unsigned b1) {
    asm volatile(
        "mma.sync.aligned.m16n8k8.row.col.f32.tf32.tf32.f32 "
        "{%0,%1,%2,%3}, {%4,%5,%6,%7}, {%8,%9}, {%0,%1,%2,%3};"
        : "+f"(d[0]), "+f"(d[1]), "+f"(d[2]), "+f"(d[3])
        : "r"(a[0]), "r"(a[1]), "r"(a[2]), "r"(a[3]), "r"(b0), "r"(b1));
}
__device__ __forceinline__ void cp4z(unsigned dst, const void* src, int sz) {
    asm volatile("cp.async.ca.shared.global [%0], [%1], 4, %2;\n"
                 :: "r"(dst), "l"(src), "r"(sz));
}
__device__ __forceinline__ void cp16(unsigned dst, const void* src) {
    asm volatile("cp.async.cg.shared.global [%0], [%1], 16;\n"
                 :: "r"(dst), "l"(src));
}
#define CP_COMMIT() asm volatile("cp.async.commit_group;\n" ::: "memory")
#define CP_WAIT1()  asm volatile("cp.async.wait_group 1;\n" ::: "memory")
#define CP_WAIT0()  asm volatile("cp.async.wait_group 0;\n" ::: "memory")

// ---------------------------------------------------------------------------
// Weight pre-split + pack (KC=16 tiles). Row map: [0,160)=w0, [160,544)=ws.
// ---------------------------------------------------------------------------
__global__ void k_wsplit(const float* __restrict__ w0,
                         const float* __restrict__ ws) {
    int i = blockIdx.x * 256 + threadIdx.x;
    if (i >= WROWS * Hh) return;
    int r = i / Hh, n = i % Hh;
    float v;
    if (r < KT0) v = (r < INF) ? w0[r * Hh + n] : 0.f;
    else         v = ws[(long long)(r - KT0) * Hh + n];
    unsigned h = f2tf32(v);
    unsigned l = f2tf32(v - __uint_as_float(h));
    int tile = r >> 4, kk = r & 15;
    int ks = kk >> 3, rr = kk & 7, tig = rr & 3, hi = rr >> 2;
    long long cell = ((long long)(tile * 2 + ks) * 128 + n) * 4 + tig;
    g_wp[cell * 4 + hi]     = h;
    g_wp[cell * 4 + 2 + hi] = l;
}

// ---------------------------------------------------------------------------
// Dtype sniff (int64 vs int32 indices)
// ---------------------------------------------------------------------------
__global__ void k_sniff(const int* __restrict__ ei32) {
    __shared__ int ok;
    if (threadIdx.x == 0) ok = 1;
    __syncthreads();
    if (ei32[2 * threadIdx.x + 1] != 0) ok = 0;
    __syncthreads();
    if (threadIdx.x == 0) g_is64 = ok;
}
__device__ __forceinline__ int load_idx(const void* p, long long i) {
    return g_is64 ? (int)((const long long*)p)[i] : ((const int*)p)[i];
}

__global__ void k_zero() {
    int i = blockIdx.x * blockDim.x + threadIdx.x;
    int stride = gridDim.x * blockDim.x;
    for (int j = i; j < Nn; j += stride) { g_deg[j] = 0; g_fill[j] = 0; }
    for (int j = i; j < Gg * Hh; j += stride) g_pool[j] = 0.f;
    for (int j = i; j < Gg; j += stride) g_cnt[j] = 0.f;
}

__global__ void k_deg(const void* __restrict__ ei) {
    int e = blockIdx.x * blockDim.x + threadIdx.x;
    if (e < Ee) atomicAdd(&g_deg[load_idx(ei, (long long)Ee + e)], 1);
}

// ---------------------------------------------------------------------------
// Multi-block exclusive scan of g_deg -> g_rowptr
// ---------------------------------------------------------------------------
__global__ __launch_bounds__(1024) void k_scan1() {
    __shared__ int wsum[32];
    int i = blockIdx.x * 1024 + threadIdx.x;
    int lane = threadIdx.x & 31, wid = threadIdx.x >> 5;
    int v = (i < Nn) ? g_deg[i] : 0;
    #pragma unroll
    for (int o = 16; o; o >>= 1) v += __shfl_down_sync(0xFFFFFFFFu, v, o);
    if (lane == 0) wsum[wid] = v;
    __syncthreads();
    if (wid == 0) {
        int s = wsum[lane];
        #pragma unroll
        for (int o = 16; o; o >>= 1) s += __shfl_down_sync(0xFFFFFFFFu, s, o);
        if (lane == 0) g_bsum[blockIdx.x] = s;
    }
}

__global__ __launch_bounds__(128) void k_scan2() {
    __shared__ int wsum[4];
    int tid = threadIdx.x, lane = tid & 31, wid = tid >> 5;
    int v = (tid < NBLK) ? g_bsum[tid] : 0;
    int incl = v;
    #pragma unroll
    for (int o = 1; o < 32; o <<= 1) {
        int t = __shfl_up_sync(0xFFFFFFFFu, incl, o);
        if (lane >= o) incl += t;
    }
    if (lane == 31) wsum[wid] = incl;
    __syncthreads();
    int off = 0;
    #pragma unroll
    for (int w = 0; w < 4; w++) if (w < wid) off += wsum[w];
    if (tid < NBLK) g_bsum[tid] = off + incl - v;
    if (tid == 0) g_rowptr[Nn] = Ee;
}

__global__ __launch_bounds__(1024) void k_scan3() {
    __shared__ int wsum[32];
    int i = blockIdx.x * 1024 + threadIdx.x;
    int lane = threadIdx.x & 31, wid = threadIdx.x >> 5;
    int v = (i < Nn) ? g_deg[i] : 0;
    int incl = v;
    #pragma unroll
    for (int o = 1; o < 32; o <<= 1) {
        int t = __shfl_up_sync(0xFFFFFFFFu, incl, o);
        if (lane >= o) incl += t;
    }
    if (lane == 31) wsum[wid] = incl;
    __syncthreads();
    if (wid == 0) {
        int w = wsum[lane];
        int winc = w;
        #pragma unroll
        for (int o = 1; o < 32; o <<= 1) {
            int t = __shfl_up_sync(0xFFFFFFFFu, winc, o);
            if (lane >= o) winc += t;
        }
        wsum[lane] = winc - w;
    }
    __syncthreads();
    if (i < Nn) {
        g_rowptr[i] = g_bsum[blockIdx.x] + wsum[wid] + (incl - v);
        g_dis[i] = rsqrtf((float)v + 1.0f);
    }
}

__global__ void k_fill(const void* __restrict__ ei) {
    int e = blockIdx.x * blockDim.x + threadIdx.x;
    if (e < Ee) {
        int s = load_idx(ei, e);
        int d = load_idx(ei, (long long)Ee + e);
        int pos = g_rowptr[d] + atomicAdd(&g_fill[d], 1);
        g_col[pos] = s;
    }
}

// ---------------------------------------------------------------------------
// Prefetch one KC=16 tile: A (128 rows) raw f32 (4B cp.async, zfill OOB);
// B = verbatim copy of the pre-packed tile (contiguous 16KB, 16B cp.async).
// ---------------------------------------------------------------------------
__device__ __forceinline__ void gemm_prefetch(
    const float* __restrict__ src, int lda, int K, int m0, int tid, int k0,
    unsigned aDst, unsigned bDst, int tile)
{
    #pragma unroll
    for (int t = 0; t < 8; t++) {
        int e = t * 256 + tid;                 // 2048 A elems
        int m = e >> 4, kk = e & 15;
        int row = m0 + m, kg = k0 + kk;
        bool ok = (row < Nn) && (kg < K);
        const float* sp = ok ? (src + (long long)row * lda + kg) : src;
        cp4z(aDst + (unsigned)((m * SA_STR + kk) * 4), sp, ok ? 4 : 0);
    }
    const unsigned* wsrc = &g_wp[(long long)tile * CELLS_PER_TILE * 4];
    #pragma unroll
    for (int t = 0; t < 4; t++) {
        int c = t * 256 + tid;                 // 1024 cells
        cp16(bDst + (unsigned)(c * 16), wsrc + (long long)c * 4);
    }
}

// ---------------------------------------------------------------------------
// Pipelined tensor-core GEMM (3xTF32): g_h[row,:] = in[row,:] @ W (UNSCALED).
// Block tile 128x128, 8 warps = 4(M)x2(N), warp tile 32x64: each B LDS.128
// feeds TWO M-fragments (6 MMAs) -> B smem traffic per MMA halves.
// in == nullptr means "read g_act".
// ---------------------------------------------------------------------------
__global__ __launch_bounds__(256, 2) void k_gemm(const float* __restrict__ in,
                                                 int lda, int K, int nT,
                                                 int tile_base) {
    extern __shared__ __align__(16) float smem_dyn[];
    const float* src = in ? in : g_act;

    int tid  = threadIdx.x;
    int warp = tid >> 5, lane = tid & 31;
    int gid  = lane >> 2, tig = lane & 3;
    int wm   = warp >> 1, wn = warp & 1;
    int m0   = blockIdx.x * MT;
    int mw   = m0 + wm * 32;                 // warp covers 32 rows
    int n0w  = wn * 64;

    unsigned smem_base = (unsigned)__cvta_generic_to_shared(smem_dyn);

    float acc[2][8][4];
    #pragma unroll
    for (int mf = 0; mf < 2; mf++)
        #pragma unroll
        for (int f = 0; f < 8; f++)
            #pragma unroll
            for (int j = 0; j < 4; j++) acc[mf][f][j] = 0.f;

    gemm_prefetch(src, lda, K, m0, tid, 0,
                  smem_base + SA_OFF(0) * 4,
                  smem_base + SBP_OFF(0) * 4, tile_base);
    CP_COMMIT();

    for (int t = 0; t < nT; t++) {
        int buf = t & 1;
        if (t + 1 < nT) {
            int nb = (t + 1) & 1;
            gemm_prefetch(src, lda, K, m0, tid, (t + 1) * KC,
                          smem_base + SA_OFF(nb) * 4,
                          smem_base + SBP_OFF(nb) * 4, tile_base + t + 1);
            CP_COMMIT();
            CP_WAIT1();
        } else {
            CP_WAIT0();
        }
        __syncthreads();

        const float* sA  = smem_dyn + SA_OFF(buf);
        const uint4* sBp = reinterpret_cast<const uint4*>(
            reinterpret_cast<const unsigned*>(smem_dyn) + SBP_OFF(buf));

        #pragma unroll
        for (int ks = 0; ks < KC / 8; ks++) {
            int kb = ks * 8;
            unsigned ah[2][4], al[2][4];
            #pragma unroll
            for (int mf = 0; mf < 2; mf++) {
                int rbase = (wm * 32 + mf * 16 + gid) * SA_STR;
                float a0 = sA[rbase + kb + tig];
                float a1 = sA[rbase + 8 * SA_STR + kb + tig];
                float a2 = sA[rbase + kb + tig + 4];
                float a3 = sA[rbase + 8 * SA_STR + kb + tig + 4];
                ah[mf][0] = f2tf32(a0); ah[mf][1] = f2tf32(a1);
                ah[mf][2] = f2tf32(a2); ah[mf][3] = f2tf32(a3);
                al[mf][0] = f2tf32(a0 - __uint_as_float(ah[mf][0]));
                al[mf][1] = f2tf32(a1 - __uint_as_float(ah[mf][1]));
                al[mf][2] = f2tf32(a2 - __uint_as_float(ah[mf][2]));
                al[mf][3] = f2tf32(a3 - __uint_as_float(ah[mf][3]));
            }

            #pragma unroll
            for (int nf = 0; nf < 8; nf++) {
                int nb2 = n0w + nf * 8 + gid;
                uint4 b = sBp[(ks * 128 + nb2) * 4 + tig];
                #pragma unroll
                for (int mf = 0; mf < 2; mf++) {
                    mma_tf32(acc[mf][nf], ah[mf], b.x, b.y);   // hi*hi
                    mma_tf32(acc[mf][nf], al[mf], b.x, b.y);   // lo*hi
                    mma_tf32(acc[mf][nf], ah[mf], b.z, b.w);   // hi*lo
                }
            }
        }
        __syncthreads();
    }

    #pragma unroll
    for (int mf = 0; mf < 2; mf++) {
        int r0 = mw + mf * 16 + gid, r1 = r0 + 8;
        #pragma unroll
        for (int nf = 0; nf < 8; nf++) {
            int c = n0w + nf * 8 + tig * 2;
            if (r0 < Nn) {
                float2 o = make_float2(acc[mf][nf][0], acc[mf][nf][1]);
                *reinterpret_cast<float2*>(&g_h[(long long)r0 * Hh + c]) = o;
            }
            if (r1 < Nn) {
                float2 o = make_float2(acc[mf][nf][2], acc[mf][nf][3]);
                *reinterpret_cast<float2*>(&g_h[(long long)r1 * Hh + c]) = o;
            }
        }
    }
}

// ---------------------------------------------------------------------------
// Aggregation + bias + BN(eval) + ReLU (one warp per node, float4 per lane).
// out = relu(gamma*BN_INV*(dis[dst]*(sum dis[src]*v[src] + dis[dst]*v[dst]) + b) + beta)
// ---------------------------------------------------------------------------
__global__ __launch_bounds__(128) void k_agg(const float* __restrict__ bias,
                                             const float* __restrict__ gamma,
                                             const float* __restrict__ beta) {
    int warp = threadIdx.x >> 5, lane = threadIdx.x & 31;
    int node = blockIdx.x * 4 + warp;
    if (node >= Nn) return;

    const float4* h4 = reinterpret_cast<const float4*>(g_h);
    int r0 = g_rowptr[node], r1 = g_rowptr[node + 1];
    float d = g_dis[node];

    float4 vs = h4[(long long)node * 32 + lane];
    float4 a = make_float4(d * vs.x, d * vs.y, d * vs.z, d * vs.w);

    int e = r0;
    for (; e + 4 <= r1; e += 4) {
        int c0 = g_col[e], c1 = g_col[e + 1], c2 = g_col[e + 2], c3 = g_col[e + 3];
        float s0 = g_dis[c0], s1 = g_dis[c1], s2 = g_dis[c2], s3 = g_dis[c3];
        float4 v0 = h4[(long long)c0 * 32 + lane];
        float4 v1 = h4[(long long)c1 * 32 + lane];
        float4 v2 = h4[(long long)c2 * 32 + lane];
        float4 v3 = h4[(long long)c3 * 32 + lane];
        a.x += fmaf(s0, v0.x, fmaf(s1, v1.x, fmaf(s2, v2.x, s3 * v3.x)));
        a.y += fmaf(s0, v0.y, fmaf(s1, v1.y, fmaf(s2, v2.y, s3 * v3.y)));
        a.z += fmaf(s0, v0.z, fmaf(s1, v1.z, fmaf(s2, v2.z, s3 * v3.z)));
        a.w += fmaf(s0, v0.w, fmaf(s1, v1.w, fmaf(s2, v2.w, s3 * v3.w)));
    }
    for (; e < r1; e++) {
        int c = g_col[e];
        float s = g_dis[c];
        float4 v = h4[(long long)c * 32 + lane];
        a.x = fmaf(s, v.x, a.x); a.y = fmaf(s, v.y, a.y);
        a.z = fmaf(s, v.z, a.z); a.w = fmaf(s, v.w, a.w);
    }

    float4 bb = reinterpret_cast<const float4*>(bias)[lane];
    float4 gm = reinterpret_cast<const float4*>(gamma)[lane];
    float4 bt = reinterpret_cast<const float4*>(beta)[lane];
    float4 o;
    o.x = fmaxf(fmaf(gm.x * BN_INV, fmaf(d, a.x, bb.x), bt.x), 0.f);
    o.y = fmaxf(fmaf(gm.y * BN_INV, fmaf(d, a.y, bb.y), bt.y), 0.f);
    o.z = fmaxf(fmaf(gm.z * BN_INV, fmaf(d, a.z, bb.z), bt.z), 0.f);
    o.w = fmaxf(fmaf(gm.w * BN_INV, fmaf(d, a.w, bb.w), bt.w), 0.f);
    reinterpret_cast<float4*>(g_act)[(long long)node * 32 + lane] = o;
}

// ---------------------------------------------------------------------------
// Segmented mean pool over sorted batch
// ---------------------------------------------------------------------------
__global__ __launch_bounds__(128) void k_pool(const void* __restrict__ batch) {
    int warp = threadIdx.x >> 5, lane = threadIdx.x & 31;
    int base = (blockIdx.x * 4 + warp) * 32;
    if (base >= Nn) return;
    int end = base + 32 < Nn ? base + 32 : Nn;

    const float4* a4 = reinterpret_cast<const float4*>(g_act);
    float4 acc = make_float4(0.f, 0.f, 0.f, 0.f);
    int cur = load_idx(batch, base);
    int cnt = 0;

    for (int n = base; n < end; n++) {
        int g = load_idx(batch, n);
        if (g != cur) {
            float* dst = &g_pool[cur * Hh + lane * 4];
            atomicAdd(dst + 0, acc.x); atomicAdd(dst + 1, acc.y);
            atomicAdd(dst + 2, acc.z); atomicAdd(dst + 3, acc.w);
            if (lane == 0) atomicAdd(&g_cnt[cur], (float)cnt);
            acc = make_float4(0.f, 0.f, 0.f, 0.f);
            cnt = 0; cur = g;
        }
        float4 v = a4[(long long)n * 32 + lane];
        acc.x += v.x; acc.y += v.y; acc.z += v.z; acc.w += v.w;
        cnt++;
    }
    float* dst = &g_pool[cur * Hh + lane * 4];
    atomicAdd(dst + 0, acc.x); atomicAdd(dst + 1, acc.y);
    atomicAdd(dst + 2, acc.z); atomicAdd(dst + 3, acc.w);
    if (lane == 0) atomicAdd(&g_cnt[cur], (float)cnt);
}

// ---------------------------------------------------------------------------
// Head MLP
// ---------------------------------------------------------------------------
__global__ __launch_bounds__(64) void k_head(const float* __restrict__ wc1,
                                             const float* __restrict__ bc1,
                                             const float* __restrict__ wc2,
                                             const float* __restrict__ bc2,
                                             float* __restrict__ out) {
    __shared__ float mean[128];
    __shared__ float part[2];
    int g = blockIdx.x, t = threadIdx.x;
    float inv = 1.f / fmaxf(g_cnt[g], 1.f);
    mean[t]      = g_pool[g * Hh + t] * inv;
    mean[t + 64] = g_pool[g * Hh + 64 + t] * inv;
    __syncthreads();

    float z = bc1[t];
    #pragma unroll 8
    for (int k = 0; k < 128; k++)
        z = fmaf(mean[k], wc1[k * 64 + t], z);
    z = fmaxf(z, 0.f) * wc2[t];

    #pragma unroll
    for (int o = 16; o; o >>= 1) z += __shfl_down_sync(0xFFFFFFFFu, z, o);
    if ((t & 31) == 0) part[t >> 5] = z;
    __syncthreads();
    if (t == 0) out[g] = part[0] + part[1] + bc2[0];
}

// ---------------------------------------------------------------------------
// Launch — profiled slot #4 = layer-0 GEMM
// ---------------------------------------------------------------------------
extern "C" void kernel_launch(void* const* d_in, const int* in_sizes, int n_in,
                              void* d_out, int out_size) {
    const float* x      = (const float*)d_in[0];
    const void*  ei     = d_in[1];
    const void*  batch  = d_in[2];
    const float* w0     = (const float*)d_in[3];
    const float* b0     = (const float*)d_in[4];
    const float* ws     = (const float*)d_in[5];
    const float* bs     = (const float*)d_in[6];
    const float* gammas = (const float*)d_in[7];
    const float* betas  = (const float*)d_in[8];
    const float* wc1    = (const float*)d_in[9];
    const float* bc1    = (const float*)d_in[10];
    const float* wc2    = (const float*)d_in[11];
    const float* bc2    = (const float*)d_in[12];
    float* out = (float*)d_out;

    cudaFuncSetAttribute(k_gemm, cudaFuncAttributeMaxDynamicSharedMemorySize,
                         GSMEM_BYTES);

    const int gemm_grid = (Nn + MT - 1) / MT;
    const int agg_grid  = (Nn + 3) / 4;

    k_wsplit<<<(WROWS * Hh + 255) / 256, 256>>>(w0, ws);            // 1
    k_sniff<<<1, 256>>>((const int*)ei);                            // 2
    k_zero<<<1024, 256>>>();                                        // 3
    k_gemm<<<gemm_grid, 256, GSMEM_BYTES>>>(x, INF, INF, NT0, 0);   // 4 (profiled)
    k_deg<<<(Ee + 255) / 256, 256>>>(ei);
    k_scan1<<<NBLK, 1024>>>();
    k_scan2<<<1, 128>>>();
    k_scan3<<<NBLK, 1024>>>();
    k_fill<<<(Ee + 255) / 256, 256>>>(ei);

    k_agg<<<agg_grid, 128>>>(b0, gammas, betas);                    // layer 0
    for (int l = 1; l < 4; l++) {
        k_gemm<<<gemm_grid, 256, GSMEM_BYTES>>>(nullptr, Hh, Hh, NTL,
                                                NT0 + (l - 1) * NTL);
        k_agg<<<agg_grid, 128>>>(bs + (size_t)(l - 1) * Hh,
                                 gammas + (size_t)l * Hh,
                                 betas + (size_t)l * Hh);
    }

    k_pool<<<(Nn + 127) / 128, 128>>>(batch);
    k_head<<<Gg, 64>>>(wc1, bc1, wc2, bc2, out);
}

// round 16
// speedup vs baseline: 1.1790x; 1.1790x over previous
#include <cuda_runtime.h>

// Problem constants
#define Nn   100000
#define Ee   800000
#define Gg   4096
#define INF  143
#define Hh   128
#define BN_INV 0.9999950000374997f   // rsqrt(1 + 1e-5)
#define NBLK ((Nn + 1023) / 1024)    // 98 scan blocks
#define KC   16                      // k-tile
#define KT0  160                     // layer-0 K padded to tile multiple
#define WROWS (KT0 + 3 * Hh)         // 544 pre-split weight rows
#define NT0  (KT0 / KC)              // 10 layer-0 tiles
#define NTL  (Hh / KC)               // 8 tiles per later layer
#define NTILES (WROWS / KC)          // 34 weight k-tiles
#define CELLS_PER_TILE (2 * 128 * 4) // [ks][n][tig] cells, 8B each (2xTF32)

// Dynamic smem layout (32-bit words): A raw x2 (stride 20), B packed x2
#define SA_STR 20
#define SA_W   (64 * SA_STR)          // 1280
#define SBP_W  (CELLS_PER_TILE * 2)   // 2048 words (8B cells)
#define SA_OFF(b)  ((b) * SA_W)
#define SBP_OFF(b) (2 * SA_W + (b) * SBP_W)
#define GSMEM_BYTES ((2 * SA_W + 2 * SBP_W) * 4)   // 26624

// ---------------------------------------------------------------------------
// Device scratch
// ---------------------------------------------------------------------------
__device__ __align__(16) float g_h[Nn * Hh];     // h @ W (UNSCALED), per layer
__device__ __align__(16) float g_act[Nn * Hh];   // post BN+ReLU activations
__device__ float g_dis[Nn];
__device__ int   g_deg[Nn];
__device__ int   g_rowptr[Nn + 1];
__device__ int   g_fill[Nn];
__device__ int   g_col[Ee];
__device__ __align__(16) float g_pool[Gg * Hh];
__device__ float g_cnt[Gg];
__device__ int   g_is64;
__device__ int   g_bsum[NBLK];
// Pre-split + PRE-PACKED weights (2xTF32): cell = {bh(k), bh(k+4)}
__device__ __align__(16) unsigned g_wp[NTILES * CELLS_PER_TILE * 2];

// ---------------------------------------------------------------------------
// TF32 / cp.async helpers
// ---------------------------------------------------------------------------
__device__ __forceinline__ unsigned f2tf32(float x) {
    unsigned r;
    asm("cvt.rna.tf32.f32 %0, %1;" : "=r"(r) : "f"(x));
    return r;
}
__device__ __forceinline__ void mma_tf32(float* d, const unsigned* a,
                                         unsigned b0, unsigned b1) {
    asm volatile(
        "mma.sync.aligned.m16n8k8.row.col.f32.tf32.tf32.f32 "
        "{%0,%1,%2,%3}, {%4,%5,%6,%7}, {%8,%9}, {%0,%1,%2,%3};"
        : "+f"(d[0]), "+f"(d[1]), "+f"(d[2]), "+f"(d[3])
        : "r"(a[0]), "r"(a[1]), "r"(a[2]), "r"(a[3]), "r"(b0), "r"(b1));
}
__device__ __forceinline__ void cp4z(unsigned dst, const void* src, int sz) {
    asm volatile("cp.async.ca.shared.global [%0], [%1], 4, %2;\n"
                 :: "r"(dst), "l"(src), "r"(sz));
}
__device__ __forceinline__ void cp16(unsigned dst, const void* src) {
    asm volatile("cp.async.cg.shared.global [%0], [%1], 16;\n"
                 :: "r"(dst), "l"(src));
}
#define CP_COMMIT() asm volatile("cp.async.commit_group;\n" ::: "memory")
#define CP_WAIT1()  asm volatile("cp.async.wait_group 1;\n" ::: "memory")
#define CP_WAIT0()  asm volatile("cp.async.wait_group 0;\n" ::: "memory")

// ---------------------------------------------------------------------------
// Weight pre-split + pack (KC=16 tiles, 2xTF32: hi only).
// Row map: [0,160)=w0, [160,544)=ws. For row r, col n: tile=r/16, kk=r%16,
// ks=kk>>3, rr=kk&7, tig=rr&3, hi=rr>>2. Cell=((tile*2+ks)*128+n)*4+tig.
// ---------------------------------------------------------------------------
__global__ void k_wsplit(const float* __restrict__ w0,
                         const float* __restrict__ ws) {
    int i = blockIdx.x * 256 + threadIdx.x;
    if (i >= WROWS * Hh) return;
    int r = i / Hh, n = i % Hh;
    float v;
    if (r < KT0) v = (r < INF) ? w0[r * Hh + n] : 0.f;
    else         v = ws[(long long)(r - KT0) * Hh + n];
    unsigned h = f2tf32(v);
    int tile = r >> 4, kk = r & 15;
    int ks = kk >> 3, rr = kk & 7, tig = rr & 3, hi = rr >> 2;
    long long cell = ((long long)(tile * 2 + ks) * 128 + n) * 4 + tig;
    g_wp[cell * 2 + hi] = h;
}

// ---------------------------------------------------------------------------
// Dtype sniff (int64 vs int32 indices)
// ---------------------------------------------------------------------------
__global__ void k_sniff(const int* __restrict__ ei32) {
    __shared__ int ok;
    if (threadIdx.x == 0) ok = 1;
    __syncthreads();
    if (ei32[2 * threadIdx.x + 1] != 0) ok = 0;
    __syncthreads();
    if (threadIdx.x == 0) g_is64 = ok;
}
__device__ __forceinline__ int load_idx(const void* p, long long i) {
    return g_is64 ? (int)((const long long*)p)[i] : ((const int*)p)[i];
}

__global__ void k_zero() {
    int i = blockIdx.x * blockDim.x + threadIdx.x;
    int stride = gridDim.x * blockDim.x;
    for (int j = i; j < Nn; j += stride) { g_deg[j] = 0; g_fill[j] = 0; }
    for (int j = i; j < Gg * Hh; j += stride) g_pool[j] = 0.f;
    for (int j = i; j < Gg; j += stride) g_cnt[j] = 0.f;
}

__global__ void k_deg(const void* __restrict__ ei) {
    int e = blockIdx.x * blockDim.x + threadIdx.x;
    if (e < Ee) atomicAdd(&g_deg[load_idx(ei, (long long)Ee + e)], 1);
}

// ---------------------------------------------------------------------------
// Multi-block exclusive scan of g_deg -> g_rowptr
// ---------------------------------------------------------------------------
__global__ __launch_bounds__(1024) void k_scan1() {
    __shared__ int wsum[32];
    int i = blockIdx.x * 1024 + threadIdx.x;
    int lane = threadIdx.x & 31, wid = threadIdx.x >> 5;
    int v = (i < Nn) ? g_deg[i] : 0;
    #pragma unroll
    for (int o = 16; o; o >>= 1) v += __shfl_down_sync(0xFFFFFFFFu, v, o);
    if (lane == 0) wsum[wid] = v;
    __syncthreads();
    if (wid == 0) {
        int s = wsum[lane];
        #pragma unroll
        for (int o = 16; o; o >>= 1) s += __shfl_down_sync(0xFFFFFFFFu, s, o);
        if (lane == 0) g_bsum[blockIdx.x] = s;
    }
}

__global__ __launch_bounds__(128) void k_scan2() {
    __shared__ int wsum[4];
    int tid = threadIdx.x, lane = tid & 31, wid = tid >> 5;
    int v = (tid < NBLK) ? g_bsum[tid] : 0;
    int incl = v;
    #pragma unroll
    for (int o = 1; o < 32; o <<= 1) {
        int t = __shfl_up_sync(0xFFFFFFFFu, incl, o);
        if (lane >= o) incl += t;
    }
    if (lane == 31) wsum[wid] = incl;
    __syncthreads();
    int off = 0;
    #pragma unroll
    for (int w = 0; w < 4; w++) if (w < wid) off += wsum[w];
    if (tid < NBLK) g_bsum[tid] = off + incl - v;
    if (tid == 0) g_rowptr[Nn] = Ee;
}

__global__ __launch_bounds__(1024) void k_scan3() {
    __shared__ int wsum[32];
    int i = blockIdx.x * 1024 + threadIdx.x;
    int lane = threadIdx.x & 31, wid = threadIdx.x >> 5;
    int v = (i < Nn) ? g_deg[i] : 0;
    int incl = v;
    #pragma unroll
    for (int o = 1; o < 32; o <<= 1) {
        int t = __shfl_up_sync(0xFFFFFFFFu, incl, o);
        if (lane >= o) incl += t;
    }
    if (lane == 31) wsum[wid] = incl;
    __syncthreads();
    if (wid == 0) {
        int w = wsum[lane];
        int winc = w;
        #pragma unroll
        for (int o = 1; o < 32; o <<= 1) {
            int t = __shfl_up_sync(0xFFFFFFFFu, winc, o);
            if (lane >= o) winc += t;
        }
        wsum[lane] = winc - w;
    }
    __syncthreads();
    if (i < Nn) {
        g_rowptr[i] = g_bsum[blockIdx.x] + wsum[wid] + (incl - v);
        g_dis[i] = rsqrtf((float)v + 1.0f);
    }
}

__global__ void k_fill(const void* __restrict__ ei) {
    int e = blockIdx.x * blockDim.x + threadIdx.x;
    if (e < Ee) {
        int s = load_idx(ei, e);
        int d = load_idx(ei, (long long)Ee + e);
        int pos = g_rowptr[d] + atomicAdd(&g_fill[d], 1);
        g_col[pos] = s;
    }
}

// ---------------------------------------------------------------------------
// Prefetch one KC=16 tile: A raw f32 (4B cp.async, zfill OOB);
// B = verbatim copy of the pre-packed tile (contiguous 8KB, 16B cp.async).
// ---------------------------------------------------------------------------
__device__ __forceinline__ void gemm_prefetch(
    const float* __restrict__ src, int lda, int K, int m0, int tid, int k0,
    unsigned aDst, unsigned bDst, int tile)
{
    #pragma unroll
    for (int t = 0; t < 4; t++) {
        int e = t * 256 + tid;                 // 1024 A elems
        int m = e >> 4, kk = e & 15;
        int row = m0 + m, kg = k0 + kk;
        bool ok = (row < Nn) && (kg < K);
        const float* sp = ok ? (src + (long long)row * lda + kg) : src;
        cp4z(aDst + (unsigned)((m * SA_STR + kk) * 4), sp, ok ? 4 : 0);
    }
    const unsigned* wsrc = &g_wp[(long long)tile * CELLS_PER_TILE * 2];
    #pragma unroll
    for (int t = 0; t < 2; t++) {
        int c = t * 256 + tid;                 // 512 x 16B chunks = 8KB
        cp16(bDst + (unsigned)(c * 16), wsrc + (long long)c * 4);
    }
}

// ---------------------------------------------------------------------------
// Pipelined tensor-core GEMM (2xTF32: hi*hi + lo*hi):
//   g_h[row,:] = in[row,:] @ W (UNSCALED).
// KC=16, 26KB smem, 3 CTAs/SM. B operands per (nf, k8-step) = ONE LDS.64.
// in == nullptr means "read g_act".
// ---------------------------------------------------------------------------
__global__ __launch_bounds__(256, 3) void k_gemm(const float* __restrict__ in,
                                                 int lda, int K, int nT,
                                                 int tile_base) {
    extern __shared__ __align__(16) float smem_dyn[];
    const float* src = in ? in : g_act;

    int tid  = threadIdx.x;
    int warp = tid >> 5, lane = tid & 31;
    int gid  = lane >> 2, tig = lane & 3;
    int wm   = warp >> 1, wn = warp & 1;
    int m0   = blockIdx.x * 64;
    int mw   = m0 + wm * 16;
    int n0w  = wn * 64;

    unsigned smem_base = (unsigned)__cvta_generic_to_shared(smem_dyn);

    float acc[8][4];
    #pragma unroll
    for (int f = 0; f < 8; f++)
        #pragma unroll
        for (int j = 0; j < 4; j++) acc[f][j] = 0.f;

    gemm_prefetch(src, lda, K, m0, tid, 0,
                  smem_base + SA_OFF(0) * 4,
                  smem_base + SBP_OFF(0) * 4, tile_base);
    CP_COMMIT();

    for (int t = 0; t < nT; t++) {
        int buf = t & 1;
        if (t + 1 < nT) {
            int nb = (t + 1) & 1;
            gemm_prefetch(src, lda, K, m0, tid, (t + 1) * KC,
                          smem_base + SA_OFF(nb) * 4,
                          smem_base + SBP_OFF(nb) * 4, tile_base + t + 1);
            CP_COMMIT();
            CP_WAIT1();
        } else {
            CP_WAIT0();
        }
        __syncthreads();

        const float* sA  = smem_dyn + SA_OFF(buf);
        const uint2* sBp = reinterpret_cast<const uint2*>(
            reinterpret_cast<const unsigned*>(smem_dyn) + SBP_OFF(buf));

        #pragma unroll
        for (int ks = 0; ks < KC / 8; ks++) {
            int kb = ks * 8;
            float a0 = sA[(wm * 16 + gid) * SA_STR + kb + tig];
            float a1 = sA[(wm * 16 + gid + 8) * SA_STR + kb + tig];
            float a2 = sA[(wm * 16 + gid) * SA_STR + kb + tig + 4];
            float a3 = sA[(wm * 16 + gid + 8) * SA_STR + kb + tig + 4];
            unsigned ah[4] = { f2tf32(a0), f2tf32(a1), f2tf32(a2), f2tf32(a3) };
            unsigned al[4] = {
                f2tf32(a0 - __uint_as_float(ah[0])),
                f2tf32(a1 - __uint_as_float(ah[1])),
                f2tf32(a2 - __uint_as_float(ah[2])),
                f2tf32(a3 - __uint_as_float(ah[3])) };

            #pragma unroll
            for (int nf = 0; nf < 8; nf++) {
                int nb2 = n0w + nf * 8 + gid;
                uint2 b = sBp[(ks * 128 + nb2) * 4 + tig];
                mma_tf32(acc[nf], ah, b.x, b.y);   // hi*hi
                mma_tf32(acc[nf], al, b.x, b.y);   // lo*hi
            }
        }
        __syncthreads();
    }

    int r0 = mw + gid, r1 = mw + gid + 8;
    #pragma unroll
    for (int nf = 0; nf < 8; nf++) {
        int c = n0w + nf * 8 + tig * 2;
        if (r0 < Nn) {
            float2 o = make_float2(acc[nf][0], acc[nf][1]);
            *reinterpret_cast<float2*>(&g_h[(long long)r0 * Hh + c]) = o;
        }
        if (r1 < Nn) {
            float2 o = make_float2(acc[nf][2], acc[nf][3]);
            *reinterpret_cast<float2*>(&g_h[(long long)r1 * Hh + c]) = o;
        }
    }
}

// ---------------------------------------------------------------------------
// Aggregation + bias + BN(eval) + ReLU (one warp per node, float4 per lane).
// out = relu(gamma*BN_INV*(dis[dst]*(sum dis[src]*v[src] + dis[dst]*v[dst]) + b) + beta)
// ---------------------------------------------------------------------------
__global__ __launch_bounds__(128) void k_agg(const float* __restrict__ bias,
                                             const float* __restrict__ gamma,
                                             const float* __restrict__ beta) {
    int warp = threadIdx.x >> 5, lane = threadIdx.x & 31;
    int node = blockIdx.x * 4 + warp;
    if (node >= Nn) return;

    const float4* h4 = reinterpret_cast<const float4*>(g_h);
    int r0 = g_rowptr[node], r1 = g_rowptr[node + 1];
    float d = g_dis[node];

    float4 vs = h4[(long long)node * 32 + lane];
    float4 a = make_float4(d * vs.x, d * vs.y, d * vs.z, d * vs.w);

    int e = r0;
    for (; e + 4 <= r1; e += 4) {
        int c0 = g_col[e], c1 = g_col[e + 1], c2 = g_col[e + 2], c3 = g_col[e + 3];
        float s0 = g_dis[c0], s1 = g_dis[c1], s2 = g_dis[c2], s3 = g_dis[c3];
        float4 v0 = h4[(long long)c0 * 32 + lane];
        float4 v1 = h4[(long long)c1 * 32 + lane];
        float4 v2 = h4[(long long)c2 * 32 + lane];
        float4 v3 = h4[(long long)c3 * 32 + lane];
        a.x += fmaf(s0, v0.x, fmaf(s1, v1.x, fmaf(s2, v2.x, s3 * v3.x)));
        a.y += fmaf(s0, v0.y, fmaf(s1, v1.y, fmaf(s2, v2.y, s3 * v3.y)));
        a.z += fmaf(s0, v0.z, fmaf(s1, v1.z, fmaf(s2, v2.z, s3 * v3.z)));
        a.w += fmaf(s0, v0.w, fmaf(s1, v1.w, fmaf(s2, v2.w, s3 * v3.w)));
    }
    for (; e < r1; e++) {
        int c = g_col[e];
        float s = g_dis[c];
        float4 v = h4[(long long)c * 32 + lane];
        a.x = fmaf(s, v.x, a.x); a.y = fmaf(s, v.y, a.y);
        a.z = fmaf(s, v.z, a.z); a.w = fmaf(s, v.w, a.w);
    }

    float4 bb = reinterpret_cast<const float4*>(bias)[lane];
    float4 gm = reinterpret_cast<const float4*>(gamma)[lane];
    float4 bt = reinterpret_cast<const float4*>(beta)[lane];
    float4 o;
    o.x = fmaxf(fmaf(gm.x * BN_INV, fmaf(d, a.x, bb.x), bt.x), 0.f);
    o.y = fmaxf(fmaf(gm.y * BN_INV, fmaf(d, a.y, bb.y), bt.y), 0.f);
    o.z = fmaxf(fmaf(gm.z * BN_INV, fmaf(d, a.z, bb.z), bt.z), 0.f);
    o.w = fmaxf(fmaf(gm.w * BN_INV, fmaf(d, a.w, bb.w), bt.w), 0.f);
    reinterpret_cast<float4*>(g_act)[(long long)node * 32 + lane] = o;
}

// ---------------------------------------------------------------------------
// Segmented mean pool over sorted batch
// ---------------------------------------------------------------------------
__global__ __launch_bounds__(128) void k_pool(const void* __restrict__ batch) {
    int warp = threadIdx.x >> 5, lane = threadIdx.x & 31;
    int base = (blockIdx.x * 4 + warp) * 32;
    if (base >= Nn) return;
    int end = base + 32 < Nn ? base + 32 : Nn;

    const float4* a4 = reinterpret_cast<const float4*>(g_act);
    float4 acc = make_float4(0.f, 0.f, 0.f, 0.f);
    int cur = load_idx(batch, base);
    int cnt = 0;

    for (int n = base; n < end; n++) {
        int g = load_idx(batch, n);
        if (g != cur) {
            float* dst = &g_pool[cur * Hh + lane * 4];
            atomicAdd(dst + 0, acc.x); atomicAdd(dst + 1, acc.y);
            atomicAdd(dst + 2, acc.z); atomicAdd(dst + 3, acc.w);
            if (lane == 0) atomicAdd(&g_cnt[cur], (float)cnt);
            acc = make_float4(0.f, 0.f, 0.f, 0.f);
            cnt = 0; cur = g;
        }
        float4 v = a4[(long long)n * 32 + lane];
        acc.x += v.x; acc.y += v.y; acc.z += v.z; acc.w += v.w;
        cnt++;
    }
    float* dst = &g_pool[cur * Hh + lane * 4];
    atomicAdd(dst + 0, acc.x); atomicAdd(dst + 1, acc.y);
    atomicAdd(dst + 2, acc.z); atomicAdd(dst + 3, acc.w);
    if (lane == 0) atomicAdd(&g_cnt[cur], (float)cnt);
}

// ---------------------------------------------------------------------------
// Head MLP
// ---------------------------------------------------------------------------
__global__ __launch_bounds__(64) void k_head(const float* __restrict__ wc1,
                                             const float* __restrict__ bc1,
                                             const float* __restrict__ wc2,
                                             const float* __restrict__ bc2,
                                             float* __restrict__ out) {
    __shared__ float mean[128];
    __shared__ float part[2];
    int g = blockIdx.x, t = threadIdx.x;
    float inv = 1.f / fmaxf(g_cnt[g], 1.f);
    mean[t]      = g_pool[g * Hh + t] * inv;
    mean[t + 64] = g_pool[g * Hh + 64 + t] * inv;
    __syncthreads();

    float z = bc1[t];
    #pragma unroll 8
    for (int k = 0; k < 128; k++)
        z = fmaf(mean[k], wc1[k * 64 + t], z);
    z = fmaxf(z, 0.f) * wc2[t];

    #pragma unroll
    for (int o = 16; o; o >>= 1) z += __shfl_down_sync(0xFFFFFFFFu, z, o);
    if ((t & 31) == 0) part[t >> 5] = z;
    __syncthreads();
    if (t == 0) out[g] = part[0] + part[1] + bc2[0];
}

// ---------------------------------------------------------------------------
// Launch — profiled slot #4 = layer-0 GEMM
// ---------------------------------------------------------------------------
extern "C" void kernel_launch(void* const* d_in, const int* in_sizes, int n_in,
                              void* d_out, int out_size) {
    const float* x      = (const float*)d_in[0];
    const void*  ei     = d_in[1];
    const void*  batch  = d_in[2];
    const float* w0     = (const float*)d_in[3];
    const float* b0     = (const float*)d_in[4];
    const float* ws     = (const float*)d_in[5];
    const float* bs     = (const float*)d_in[6];
    const float* gammas = (const float*)d_in[7];
    const float* betas  = (const float*)d_in[8];
    const float* wc1    = (const float*)d_in[9];
    const float* bc1    = (const float*)d_in[10];
    const float* wc2    = (const float*)d_in[11];
    const float* bc2    = (const float*)d_in[12];
    float* out = (float*)d_out;

    cudaFuncSetAttribute(k_gemm, cudaFuncAttributeMaxDynamicSharedMemorySize,
                         GSMEM_BYTES);

    const int gemm_grid = (Nn + 63) / 64;
    const int agg_grid  = (Nn + 3) / 4;

    k_wsplit<<<(WROWS * Hh + 255) / 256, 256>>>(w0, ws);            // 1
    k_sniff<<<1, 256>>>((const int*)ei);                            // 2
    k_zero<<<1024, 256>>>();                                        // 3
    k_gemm<<<gemm_grid, 256, GSMEM_BYTES>>>(x, INF, INF, NT0, 0);   // 4 (profiled)
    k_deg<<<(Ee + 255) / 256, 256>>>(ei);
    k_scan1<<<NBLK, 1024>>>();
    k_scan2<<<1, 128>>>();
    k_scan3<<<NBLK, 1024>>>();
    k_fill<<<(Ee + 255) / 256, 256>>>(ei);

    k_agg<<<agg_grid, 128>>>(b0, gammas, betas);                    // layer 0
    for (int l = 1; l < 4; l++) {
        k_gemm<<<gemm_grid, 256, GSMEM_BYTES>>>(nullptr, Hh, Hh, NTL,
                                                NT0 + (l - 1) * NTL);
        k_agg<<<agg_grid, 128>>>(bs + (size_t)(l - 1) * Hh,
                                 gammas + (size_t)l * Hh,
                                 betas + (size_t)l * Hh);
    }

    k_pool<<<(Nn + 127) / 128, 128>>>(batch);
    k_head<<<Gg, 64>>>(wc1, bc1, wc2, bc2, out);
}

// round 17
// speedup vs baseline: 1.1961x; 1.0146x over previous
#include <cuda_runtime.h>
#include <cuda_fp16.h>

// Problem constants
#define Nn   100000
#define Ee   800000
#define Gg   4096
#define INF  143
#define Hh   128
#define BN_INV 0.9999950000374997f   // rsqrt(1 + 1e-5)
#define NBLK ((Nn + 1023) / 1024)    // 98 scan blocks
#define KC   16                      // k-tile
#define KT0  160                     // layer-0 K padded to tile multiple
#define WROWS (KT0 + 3 * Hh)         // 544 pre-split weight rows
#define NT0  (KT0 / KC)              // 10 layer-0 tiles
#define NTL  (Hh / KC)               // 8 tiles per later layer
#define NTILES (WROWS / KC)          // 34 weight k-tiles
#define CELLS_PER_TILE (2 * 128 * 4) // [ks][n][tig] cells, 8B each (2xTF32)

// Dynamic smem layout (32-bit words): A raw x2 (stride 20), B packed x2
#define SA_STR 20
#define SA_W   (64 * SA_STR)          // 1280
#define SBP_W  (CELLS_PER_TILE * 2)   // 2048 words (8B cells)
#define SA_OFF(b)  ((b) * SA_W)
#define SBP_OFF(b) (2 * SA_W + (b) * SBP_W)
#define GSMEM_BYTES ((2 * SA_W + 2 * SBP_W) * 4)   // 26624

// ---------------------------------------------------------------------------
// Device scratch
// ---------------------------------------------------------------------------
__device__ __align__(16) __half g_hh[Nn * Hh];   // h @ W (UNSCALED), fp16
__device__ __align__(16) float  g_act[Nn * Hh];  // post BN+ReLU activations
__device__ float g_dis[Nn];
__device__ int   g_deg[Nn];
__device__ int   g_rowptr[Nn + 1];
__device__ int   g_fill[Nn];
__device__ int   g_col[Ee];
__device__ __align__(16) float g_pool[Gg * Hh];
__device__ float g_cnt[Gg];
__device__ int   g_is64;
__device__ int   g_bsum[NBLK];
// Pre-split + PRE-PACKED weights (2xTF32): cell = {bh(k), bh(k+4)}
__device__ __align__(16) unsigned g_wp[NTILES * CELLS_PER_TILE * 2];

// ---------------------------------------------------------------------------
// TF32 / half / cp.async helpers
// ---------------------------------------------------------------------------
__device__ __forceinline__ unsigned f2tf32(float x) {
    unsigned r;
    asm("cvt.rna.tf32.f32 %0, %1;" : "=r"(r) : "f"(x));
    return r;
}
__device__ __forceinline__ void mma_tf32(float* d, const unsigned* a,
                                         unsigned b0, unsigned b1) {
    asm volatile(
        "mma.sync.aligned.m16n8k8.row.col.f32.tf32.tf32.f32 "
        "{%0,%1,%2,%3}, {%4,%5,%6,%7}, {%8,%9}, {%0,%1,%2,%3};"
        : "+f"(d[0]), "+f"(d[1]), "+f"(d[2]), "+f"(d[3])
        : "r"(a[0]), "r"(a[1]), "r"(a[2]), "r"(a[3]), "r"(b0), "r"(b1));
}
// Register-only fp16x2 -> float2 (no address-taking; __half2_raw fields)
__device__ __forceinline__ float2 u2f2(unsigned v) {
    __half2_raw hr;
    hr.x = (unsigned short)(v & 0xFFFFu);
    hr.y = (unsigned short)(v >> 16);
    return __half22float2((__half2)hr);
}
__device__ __forceinline__ void cp4z(unsigned dst, const void* src, int sz) {
    asm volatile("cp.async.ca.shared.global [%0], [%1], 4, %2;\n"
                 :: "r"(dst), "l"(src), "r"(sz));
}
__device__ __forceinline__ void cp16(unsigned dst, const void* src) {
    asm volatile("cp.async.cg.shared.global [%0], [%1], 16;\n"
                 :: "r"(dst), "l"(src));
}
#define CP_COMMIT() asm volatile("cp.async.commit_group;\n" ::: "memory")
#define CP_WAIT1()  asm volatile("cp.async.wait_group 1;\n" ::: "memory")
#define CP_WAIT0()  asm volatile("cp.async.wait_group 0;\n" ::: "memory")

// ---------------------------------------------------------------------------
// Weight pre-split + pack (KC=16 tiles, 2xTF32: hi only).
// Row map: [0,160)=w0, [160,544)=ws. For row r, col n: tile=r/16, kk=r%16,
// ks=kk>>3, rr=kk&7, tig=rr&3, hi=rr>>2. Cell=((tile*2+ks)*128+n)*4+tig.
// ---------------------------------------------------------------------------
__global__ void k_wsplit(const float* __restrict__ w0,
                         const float* __restrict__ ws) {
    int i = blockIdx.x * 256 + threadIdx.x;
    if (i >= WROWS * Hh) return;
    int r = i / Hh, n = i % Hh;
    float v;
    if (r < KT0) v = (r < INF) ? w0[r * Hh + n] : 0.f;
    else         v = ws[(long long)(r - KT0) * Hh + n];
    unsigned h = f2tf32(v);
    int tile = r >> 4, kk = r & 15;
    int ks = kk >> 3, rr = kk & 7, tig = rr & 3, hi = rr >> 2;
    long long cell = ((long long)(tile * 2 + ks) * 128 + n) * 4 + tig;
    g_wp[cell * 2 + hi] = h;
}

// ---------------------------------------------------------------------------
// Dtype sniff (int64 vs int32 indices)
// ---------------------------------------------------------------------------
__global__ void k_sniff(const int* __restrict__ ei32) {
    __shared__ int ok;
    if (threadIdx.x == 0) ok = 1;
    __syncthreads();
    if (ei32[2 * threadIdx.x + 1] != 0) ok = 0;
    __syncthreads();
    if (threadIdx.x == 0) g_is64 = ok;
}
__device__ __forceinline__ int load_idx(const void* p, long long i) {
    return g_is64 ? (int)((const long long*)p)[i] : ((const int*)p)[i];
}

__global__ void k_zero() {
    int i = blockIdx.x * blockDim.x + threadIdx.x;
    int stride = gridDim.x * blockDim.x;
    for (int j = i; j < Nn; j += stride) { g_deg[j] = 0; g_fill[j] = 0; }
    for (int j = i; j < Gg * Hh; j += stride) g_pool[j] = 0.f;
    for (int j = i; j < Gg; j += stride) g_cnt[j] = 0.f;
}

__global__ void k_deg(const void* __restrict__ ei) {
    int e = blockIdx.x * blockDim.x + threadIdx.x;
    if (e < Ee) atomicAdd(&g_deg[load_idx(ei, (long long)Ee + e)], 1);
}

// ---------------------------------------------------------------------------
// Multi-block exclusive scan of g_deg -> g_rowptr
// ---------------------------------------------------------------------------
__global__ __launch_bounds__(1024) void k_scan1() {
    __shared__ int wsum[32];
    int i = blockIdx.x * 1024 + threadIdx.x;
    int lane = threadIdx.x & 31, wid = threadIdx.x >> 5;
    int v = (i < Nn) ? g_deg[i] : 0;
    #pragma unroll
    for (int o = 16; o; o >>= 1) v += __shfl_down_sync(0xFFFFFFFFu, v, o);
    if (lane == 0) wsum[wid] = v;
    __syncthreads();
    if (wid == 0) {
        int s = wsum[lane];
        #pragma unroll
        for (int o = 16; o; o >>= 1) s += __shfl_down_sync(0xFFFFFFFFu, s, o);
        if (lane == 0) g_bsum[blockIdx.x] = s;
    }
}

__global__ __launch_bounds__(128) void k_scan2() {
    __shared__ int wsum[4];
    int tid = threadIdx.x, lane = tid & 31, wid = tid >> 5;
    int v = (tid < NBLK) ? g_bsum[tid] : 0;
    int incl = v;
    #pragma unroll
    for (int o = 1; o < 32; o <<= 1) {
        int t = __shfl_up_sync(0xFFFFFFFFu, incl, o);
        if (lane >= o) incl += t;
    }
    if (lane == 31) wsum[wid] = incl;
    __syncthreads();
    int off = 0;
    #pragma unroll
    for (int w = 0; w < 4; w++) if (w < wid) off += wsum[w];
    if (tid < NBLK) g_bsum[tid] = off + incl - v;
    if (tid == 0) g_rowptr[Nn] = Ee;
}

__global__ __launch_bounds__(1024) void k_scan3() {
    __shared__ int wsum[32];
    int i = blockIdx.x * 1024 + threadIdx.x;
    int lane = threadIdx.x & 31, wid = threadIdx.x >> 5;
    int v = (i < Nn) ? g_deg[i] : 0;
    int incl = v;
    #pragma unroll
    for (int o = 1; o < 32; o <<= 1) {
        int t = __shfl_up_sync(0xFFFFFFFFu, incl, o);
        if (lane >= o) incl += t;
    }
    if (lane == 31) wsum[wid] = incl;
    __syncthreads();
    if (wid == 0) {
        int w = wsum[lane];
        int winc = w;
        #pragma unroll
        for (int o = 1; o < 32; o <<= 1) {
            int t = __shfl_up_sync(0xFFFFFFFFu, winc, o);
            if (lane >= o) winc += t;
        }
        wsum[lane] = winc - w;
    }
    __syncthreads();
    if (i < Nn) {
        g_rowptr[i] = g_bsum[blockIdx.x] + wsum[wid] + (incl - v);
        g_dis[i] = rsqrtf((float)v + 1.0f);
    }
}

__global__ void k_fill(const void* __restrict__ ei) {
    int e = blockIdx.x * blockDim.x + threadIdx.x;
    if (e < Ee) {
        int s = load_idx(ei, e);
        int d = load_idx(ei, (long long)Ee + e);
        int pos = g_rowptr[d] + atomicAdd(&g_fill[d], 1);
        g_col[pos] = s;
    }
}

// ---------------------------------------------------------------------------
// Prefetch one KC=16 tile: A raw f32 (4B cp.async, zfill OOB);
// B = verbatim copy of the pre-packed tile (contiguous 8KB, 16B cp.async).
// ---------------------------------------------------------------------------
__device__ __forceinline__ void gemm_prefetch(
    const float* __restrict__ src, int lda, int K, int m0, int tid, int k0,
    unsigned aDst, unsigned bDst, int tile)
{
    #pragma unroll
    for (int t = 0; t < 4; t++) {
        int e = t * 256 + tid;                 // 1024 A elems
        int m = e >> 4, kk = e & 15;
        int row = m0 + m, kg = k0 + kk;
        bool ok = (row < Nn) && (kg < K);
        const float* sp = ok ? (src + (long long)row * lda + kg) : src;
        cp4z(aDst + (unsigned)((m * SA_STR + kk) * 4), sp, ok ? 4 : 0);
    }
    const unsigned* wsrc = &g_wp[(long long)tile * CELLS_PER_TILE * 2];
    #pragma unroll
    for (int t = 0; t < 2; t++) {
        int c = t * 256 + tid;                 // 512 x 16B chunks = 8KB
        cp16(bDst + (unsigned)(c * 16), wsrc + (long long)c * 4);
    }
}

// ---------------------------------------------------------------------------
// Pipelined tensor-core GEMM (2xTF32: hi*hi + lo*hi):
//   g_hh[row,:] = fp16( in[row,:] @ W )  (UNSCALED; dis applied in k_agg).
// KC=16, 26KB smem, 3 CTAs/SM. B operands per (nf, k8-step) = ONE LDS.64.
// in == nullptr means "read g_act".
// ---------------------------------------------------------------------------
__global__ __launch_bounds__(256, 3) void k_gemm(const float* __restrict__ in,
                                                 int lda, int K, int nT,
                                                 int tile_base) {
    extern __shared__ __align__(16) float smem_dyn[];
    const float* src = in ? in : g_act;

    int tid  = threadIdx.x;
    int warp = tid >> 5, lane = tid & 31;
    int gid  = lane >> 2, tig = lane & 3;
    int wm   = warp >> 1, wn = warp & 1;
    int m0   = blockIdx.x * 64;
    int mw   = m0 + wm * 16;
    int n0w  = wn * 64;

    unsigned smem_base = (unsigned)__cvta_generic_to_shared(smem_dyn);

    float acc[8][4];
    #pragma unroll
    for (int f = 0; f < 8; f++)
        #pragma unroll
        for (int j = 0; j < 4; j++) acc[f][j] = 0.f;

    gemm_prefetch(src, lda, K, m0, tid, 0,
                  smem_base + SA_OFF(0) * 4,
                  smem_base + SBP_OFF(0) * 4, tile_base);
    CP_COMMIT();

    for (int t = 0; t < nT; t++) {
        int buf = t & 1;
        if (t + 1 < nT) {
            int nb = (t + 1) & 1;
            gemm_prefetch(src, lda, K, m0, tid, (t + 1) * KC,
                          smem_base + SA_OFF(nb) * 4,
                          smem_base + SBP_OFF(nb) * 4, tile_base + t + 1);
            CP_COMMIT();
            CP_WAIT1();
        } else {
            CP_WAIT0();
        }
        __syncthreads();

        const float* sA  = smem_dyn + SA_OFF(buf);
        const uint2* sBp = reinterpret_cast<const uint2*>(
            reinterpret_cast<const unsigned*>(smem_dyn) + SBP_OFF(buf));

        #pragma unroll
        for (int ks = 0; ks < KC / 8; ks++) {
            int kb = ks * 8;
            float a0 = sA[(wm * 16 + gid) * SA_STR + kb + tig];
            float a1 = sA[(wm * 16 + gid + 8) * SA_STR + kb + tig];
            float a2 = sA[(wm * 16 + gid) * SA_STR + kb + tig + 4];
            float a3 = sA[(wm * 16 + gid + 8) * SA_STR + kb + tig + 4];
            unsigned ah[4] = { f2tf32(a0), f2tf32(a1), f2tf32(a2), f2tf32(a3) };
            unsigned al[4] = {
                f2tf32(a0 - __uint_as_float(ah[0])),
                f2tf32(a1 - __uint_as_float(ah[1])),
                f2tf32(a2 - __uint_as_float(ah[2])),
                f2tf32(a3 - __uint_as_float(ah[3])) };

            #pragma unroll
            for (int nf = 0; nf < 8; nf++) {
                int nb2 = n0w + nf * 8 + gid;
                uint2 b = sBp[(ks * 128 + nb2) * 4 + tig];
                mma_tf32(acc[nf], ah, b.x, b.y);   // hi*hi
                mma_tf32(acc[nf], al, b.x, b.y);   // lo*hi
            }
        }
        __syncthreads();
    }

    // epilogue: convert to fp16 pairs straight from accumulators
    __half2* out2 = reinterpret_cast<__half2*>(g_hh);
    int r0 = mw + gid, r1 = mw + gid + 8;
    #pragma unroll
    for (int nf = 0; nf < 8; nf++) {
        int c = n0w + nf * 8 + tig * 2;          // even column
        if (r0 < Nn)
            out2[(long long)r0 * 64 + (c >> 1)] =
                __floats2half2_rn(acc[nf][0], acc[nf][1]);
        if (r1 < Nn)
            out2[(long long)r1 * 64 + (c >> 1)] =
                __floats2half2_rn(acc[nf][2], acc[nf][3]);
    }
}

// ---------------------------------------------------------------------------
// Aggregation + bias + BN(eval) + ReLU (one warp per node).
// g_hh is fp16 UNSCALED: per lane gather uint2 (4 halves = 8B), accumulate
// fp32: out = relu(gamma*BN_INV*(dis[dst]*(sum dis[src]*v + dis[dst]*v_self) + b) + beta)
// ---------------------------------------------------------------------------
__global__ __launch_bounds__(128) void k_agg(const float* __restrict__ bias,
                                             const float* __restrict__ gamma,
                                             const float* __restrict__ beta) {
    int warp = threadIdx.x >> 5, lane = threadIdx.x & 31;
    int node = blockIdx.x * 4 + warp;
    if (node >= Nn) return;

    const uint2* h2 = reinterpret_cast<const uint2*>(g_hh);  // 32 uint2/row
    int r0 = g_rowptr[node], r1 = g_rowptr[node + 1];
    float d = g_dis[node];

    uint2 us = h2[(long long)node * 32 + lane];
    float2 s0f = u2f2(us.x), s1f = u2f2(us.y);
    float4 a = make_float4(d * s0f.x, d * s0f.y, d * s1f.x, d * s1f.y);

    int e = r0;
    for (; e + 4 <= r1; e += 4) {
        int c0 = g_col[e], c1 = g_col[e + 1], c2 = g_col[e + 2], c3 = g_col[e + 3];
        float w0 = g_dis[c0], w1 = g_dis[c1], w2 = g_dis[c2], w3 = g_dis[c3];
        uint2 u0 = h2[(long long)c0 * 32 + lane];
        uint2 u1 = h2[(long long)c1 * 32 + lane];
        uint2 u2 = h2[(long long)c2 * 32 + lane];
        uint2 u3 = h2[(long long)c3 * 32 + lane];
        float2 p0a = u2f2(u0.x), p0b = u2f2(u0.y);
        float2 p1a = u2f2(u1.x), p1b = u2f2(u1.y);
        float2 p2a = u2f2(u2.x), p2b = u2f2(u2.y);
        float2 p3a = u2f2(u3.x), p3b = u2f2(u3.y);
        a.x += fmaf(w0, p0a.x, fmaf(w1, p1a.x, fmaf(w2, p2a.x, w3 * p3a.x)));
        a.y += fmaf(w0, p0a.y, fmaf(w1, p1a.y, fmaf(w2, p2a.y, w3 * p3a.y)));
        a.z += fmaf(w0, p0b.x, fmaf(w1, p1b.x, fmaf(w2, p2b.x, w3 * p3b.x)));
        a.w += fmaf(w0, p0b.y, fmaf(w1, p1b.y, fmaf(w2, p2b.y, w3 * p3b.y)));
    }
    for (; e < r1; e++) {
        int c = g_col[e];
        float s = g_dis[c];
        uint2 u = h2[(long long)c * 32 + lane];
        float2 pa = u2f2(u.x), pb = u2f2(u.y);
        a.x = fmaf(s, pa.x, a.x); a.y = fmaf(s, pa.y, a.y);
        a.z = fmaf(s, pb.x, a.z); a.w = fmaf(s, pb.y, a.w);
    }

    float4 bb = reinterpret_cast<const float4*>(bias)[lane];
    float4 gm = reinterpret_cast<const float4*>(gamma)[lane];
    float4 bt = reinterpret_cast<const float4*>(beta)[lane];
    float4 o;
    o.x = fmaxf(fmaf(gm.x * BN_INV, fmaf(d, a.x, bb.x), bt.x), 0.f);
    o.y = fmaxf(fmaf(gm.y * BN_INV, fmaf(d, a.y, bb.y), bt.y), 0.f);
    o.z = fmaxf(fmaf(gm.z * BN_INV, fmaf(d, a.z, bb.z), bt.z), 0.f);
    o.w = fmaxf(fmaf(gm.w * BN_INV, fmaf(d, a.w, bb.w), bt.w), 0.f);
    reinterpret_cast<float4*>(g_act)[(long long)node * 32 + lane] = o;
}

// ---------------------------------------------------------------------------
// Segmented mean pool over sorted batch
// ---------------------------------------------------------------------------
__global__ __launch_bounds__(128) void k_pool(const void* __restrict__ batch) {
    int warp = threadIdx.x >> 5, lane = threadIdx.x & 31;
    int base = (blockIdx.x * 4 + warp) * 32;
    if (base >= Nn) return;
    int end = base + 32 < Nn ? base + 32 : Nn;

    const float4* a4 = reinterpret_cast<const float4*>(g_act);
    float4 acc = make_float4(0.f, 0.f, 0.f, 0.f);
    int cur = load_idx(batch, base);
    int cnt = 0;

    for (int n = base; n < end; n++) {
        int g = load_idx(batch, n);
        if (g != cur) {
            float* dst = &g_pool[cur * Hh + lane * 4];
            atomicAdd(dst + 0, acc.x); atomicAdd(dst + 1, acc.y);
            atomicAdd(dst + 2, acc.z); atomicAdd(dst + 3, acc.w);
            if (lane == 0) atomicAdd(&g_cnt[cur], (float)cnt);
            acc = make_float4(0.f, 0.f, 0.f, 0.f);
            cnt = 0; cur = g;
        }
        float4 v = a4[(long long)n * 32 + lane];
        acc.x += v.x; acc.y += v.y; acc.z += v.z; acc.w += v.w;
        cnt++;
    }
    float* dst = &g_pool[cur * Hh + lane * 4];
    atomicAdd(dst + 0, acc.x); atomicAdd(dst + 1, acc.y);
    atomicAdd(dst + 2, acc.z); atomicAdd(dst + 3, acc.w);
    if (lane == 0) atomicAdd(&g_cnt[cur], (float)cnt);
}

// ---------------------------------------------------------------------------
// Head MLP
// ---------------------------------------------------------------------------
__global__ __launch_bounds__(64) void k_head(const float* __restrict__ wc1,
                                             const float* __restrict__ bc1,
                                             const float* __restrict__ wc2,
                                             const float* __restrict__ bc2,
                                             float* __restrict__ out) {
    __shared__ float mean[128];
    __shared__ float part[2];
    int g = blockIdx.x, t = threadIdx.x;
    float inv = 1.f / fmaxf(g_cnt[g], 1.f);
    mean[t]      = g_pool[g * Hh + t] * inv;
    mean[t + 64] = g_pool[g * Hh + 64 + t] * inv;
    __syncthreads();

    float z = bc1[t];
    #pragma unroll 8
    for (int k = 0; k < 128; k++)
        z = fmaf(mean[k], wc1[k * 64 + t], z);
    z = fmaxf(z, 0.f) * wc2[t];

    #pragma unroll
    for (int o = 16; o; o >>= 1) z += __shfl_down_sync(0xFFFFFFFFu, z, o);
    if ((t & 31) == 0) part[t >> 5] = z;
    __syncthreads();
    if (t == 0) out[g] = part[0] + part[1] + bc2[0];
}

// ---------------------------------------------------------------------------
// Launch — profiled slot #4 = layer-0 GEMM
// ---------------------------------------------------------------------------
extern "C" void kernel_launch(void* const* d_in, const int* in_sizes, int n_in,
                              void* d_out, int out_size) {
    const float* x      = (const float*)d_in[0];
    const void*  ei     = d_in[1];
    const void*  batch  = d_in[2];
    const float* w0     = (const float*)d_in[3];
    const float* b0     = (const float*)d_in[4];
    const float* ws     = (const float*)d_in[5];
    const float* bs     = (const float*)d_in[6];
    const float* gammas = (const float*)d_in[7];
    const float* betas  = (const float*)d_in[8];
    const float* wc1    = (const float*)d_in[9];
    const float* bc1    = (const float*)d_in[10];
    const float* wc2    = (const float*)d_in[11];
    const float* bc2    = (const float*)d_in[12];
    float* out = (float*)d_out;

    cudaFuncSetAttribute(k_gemm, cudaFuncAttributeMaxDynamicSharedMemorySize,
                         GSMEM_BYTES);

    const int gemm_grid = (Nn + 63) / 64;
    const int agg_grid  = (Nn + 3) / 4;

    k_wsplit<<<(WROWS * Hh + 255) / 256, 256>>>(w0, ws);            // 1
    k_sniff<<<1, 256>>>((const int*)ei);                            // 2
    k_zero<<<1024, 256>>>();                                        // 3
    k_gemm<<<gemm_grid, 256, GSMEM_BYTES>>>(x, INF, INF, NT0, 0);   // 4 (profiled)
    k_deg<<<(Ee + 255) / 256, 256>>>(ei);
    k_scan1<<<NBLK, 1024>>>();
    k_scan2<<<1, 128>>>();
    k_scan3<<<NBLK, 1024>>>();
    k_fill<<<(Ee + 255) / 256, 256>>>(ei);

    k_agg<<<agg_grid, 128>>>(b0, gammas, betas);                    // layer 0
    for (int l = 1; l < 4; l++) {
        k_gemm<<<gemm_grid, 256, GSMEM_BYTES>>>(nullptr, Hh, Hh, NTL,
                                                NT0 + (l - 1) * NTL);
        k_agg<<<agg_grid, 128>>>(bs + (size_t)(l - 1) * Hh,
                                 gammas + (size_t)l * Hh,
                                 betas + (size_t)l * Hh);
    }

    k_pool<<<(Nn + 127) / 128, 128>>>(batch);
    k_head<<<Gg, 64>>>(wc1, bc1, wc2, bc2, out);
}